// round 11
// baseline (speedup 1.0000x reference)
#include <cuda_runtime.h>
#include <cstdint>

// ============================================================================
// Router gate: x [32768, 2048] f32, w [64, 2048] f32.
// logits = x @ w^T ; probs = softmax ; top-8 vals + indices.
// Out: [probs N*64 | top_vals N*8 | indices(float) N*8]
//
// mma m16n8k8 TF32, 2-way split (x=xh+xm, w=wh+wm):
//   xh*wh -> chunk accumulator, rebased every k32 into master via RN FADD
//   xh*wm + xm*wh -> separate small-magnitude accumulator
// R11: 4-stage cp.async ring, ONE __syncthreads per k32 chunk (was 2),
//      prefetch depth 2 chunks; intra-chunk x prefetch one step ahead.
//      Tile/warp mapping and accumulation order identical to R10.
// ============================================================================

#define D 2048
#define TB 128            // tokens per CTA
#define NCH 64            // k32 chunks
#define BSTEP 4096        // B frag bytes per step
#define BCHUNK 16384      // 4 steps
#define XSTRIDE 144       // bytes per x row: 36 floats (CF swizzle)
#define XCHUNK 18432      // 128 rows * 144
#define XB 65536          // x region base (after 4 B stages)
#define EPI_STRIDE 68
#define SMEM_SZ (XB + 4 * XCHUNK)   // 139264

// weights split into tf32 h/m, HMMA B-fragment order:
// [step(256)][tile(8)][lane(32)] x uint4(bh0, bh1, bm0, bm1)
__device__ __align__(16) unsigned char g_bfrag[256 * BSTEP];

static __device__ __forceinline__ uint32_t smem_u32(const void* p) {
    uint32_t a;
    asm("{ .reg .u64 t; cvta.to.shared.u64 t, %1; cvt.u32.u64 %0, t; }"
        : "=r"(a) : "l"(p));
    return a;
}
static __device__ __forceinline__ void split2(float v, uint32_t& h, uint32_t& m) {
    asm("cvt.rna.tf32.f32 %0, %1;" : "=r"(h) : "f"(v));
    float r = v - __uint_as_float(h);
    asm("cvt.rna.tf32.f32 %0, %1;" : "=r"(m) : "f"(r));
}

#define MMA(d, a, b0_, b1_) \
    asm volatile("mma.sync.aligned.m16n8k8.row.col.f32.tf32.tf32.f32 " \
        "{%0,%1,%2,%3}, {%4,%5,%6,%7}, {%8,%9}, {%0,%1,%2,%3};" \
        : "+f"((d)[0]), "+f"((d)[1]), "+f"((d)[2]), "+f"((d)[3]) \
        : "r"((a)[0]), "r"((a)[1]), "r"((a)[2]), "r"((a)[3]), "r"(b0_), "r"(b1_))
#define MMA_ZC(d, a, b0_, b1_) \
    asm volatile("mma.sync.aligned.m16n8k8.row.col.f32.tf32.tf32.f32 " \
        "{%0,%1,%2,%3}, {%4,%5,%6,%7}, {%8,%9}, {%10,%10,%10,%10};" \
        : "=f"((d)[0]), "=f"((d)[1]), "=f"((d)[2]), "=f"((d)[3]) \
        : "r"((a)[0]), "r"((a)[1]), "r"((a)[2]), "r"((a)[3]), "r"(b0_), "r"(b1_), \
          "f"(0.0f))

#define CP16(s, g) \
    asm volatile("cp.async.cg.shared.global [%0], [%1], 16;" :: "r"(s), "l"(g) : "memory")
#define CP_COMMIT() asm volatile("cp.async.commit_group;" ::: "memory")
#define CP_WAIT2()  asm volatile("cp.async.wait_group 2;" ::: "memory")
#define CP_WAIT1()  asm volatile("cp.async.wait_group 1;" ::: "memory")
#define CP_WAIT0()  asm volatile("cp.async.wait_group 0;" ::: "memory")
#define LDS128(v, a) \
    asm volatile("ld.shared.v4.b32 {%0,%1,%2,%3}, [%4];" \
        : "=r"((v).x), "=r"((v).y), "=r"((v).z), "=r"((v).w) : "r"(a))
#define LDSF(v, a) \
    asm volatile("ld.shared.f32 %0, [%1];" : "=f"(v) : "r"(a))

// ---------------- weight prep ----------------
__global__ void prep_bfrag(const float* __restrict__ w) {
    int i = blockIdx.x * blockDim.x + threadIdx.x;   // (step*8 + tile)*32 + lane
    if (i >= 256 * 8 * 32) return;
    int lane = i & 31;
    int tile = (i >> 5) & 7;
    int step = i >> 8;
    int e = tile * 8 + (lane >> 2);
    int tq = lane & 3;
    int k0 = step * 8;
    const float* wr = w + (size_t)e * D;
    uint32_t h0, m0, h1, m1;
    split2(wr[k0 + tq],     h0, m0);
    split2(wr[k0 + tq + 4], h1, m1);
    *reinterpret_cast<uint4*>(g_bfrag + step * BSTEP + tile * 512 + lane * 16) =
        make_uint4(h0, h1, m0, m1);
}

// stage chunk c into ring stage s (B 16KB + X 16KB), one commit group
static __device__ __forceinline__ void stage_chunk(uint32_t sbase,
                                                   const unsigned char* xg,
                                                   int c, int s, int tid) {
    const unsigned char* bsrc = g_bfrag + (size_t)c * BCHUNK;
    uint32_t bd = sbase + s * BCHUNK;
    uint32_t xd = sbase + XB + s * XCHUNK;
    size_t kb = (size_t)c * 128;   // 32 floats
    CP16(bd + tid * 16,         bsrc + tid * 16);
    CP16(bd + (tid + 512) * 16, bsrc + (tid + 512) * 16);
    #pragma unroll
    for (int p = 0; p < 2; ++p) {
        int u = tid + p * 512;     // 1024 x 16B = 128 rows x 8 segs
        int row = u >> 3, seg = u & 7;
        CP16(xd + row * XSTRIDE + seg * 16,
             xg + (size_t)row * (D * 4) + kb + seg * 16);
    }
    CP_COMMIT();
}

// ---------------- main fused kernel ----------------
__global__ void __launch_bounds__(512, 1)
moe_gate(const float* __restrict__ x, float* __restrict__ out, int Ntok) {
    extern __shared__ __align__(16) float smemf[];
    const uint32_t sbase = smem_u32(smemf);
    const int tid = threadIdx.x;
    const int wid = tid >> 5;
    const int lane = tid & 31;
    const int g = lane >> 2;
    const int t4 = lane & 3;
    const int tg = wid >> 1;          // token group 0..7 (16 tokens, m16)
    const int eh = wid & 1;           // expert half 0..1 (32 experts, n32)
    const size_t t0 = (size_t)blockIdx.x * TB;
    const unsigned char* xg = reinterpret_cast<const unsigned char*>(x + t0 * D);

    float chx[4][4], ms[4][4], cc[4][4];
    #pragma unroll
    for (int i = 0; i < 4; ++i)
        #pragma unroll
        for (int j = 0; j < 4; ++j) { ms[i][j] = 0.0f; cc[i][j] = 0.0f; }

    // prologue: stage chunks 0 and 1 (two commit groups)
    stage_chunk(sbase, xg, 0, 0, tid);
    stage_chunk(sbase, xg, 1, 1, tid);

    // x fragment gather base: rows tg*16 + {g, g+8}
    const uint32_t xfrag0 = sbase + XB + (tg * 16 + g) * XSTRIDE + t4 * 4;

    for (int ch = 0; ch < NCH; ++ch) {
        // deep prefetch: issue chunk ch+2 into stage (ch+2)&3, then wait for ch
        if (ch + 2 < NCH) {
            stage_chunk(sbase, xg, ch + 2, (ch + 2) & 3, tid);
            CP_WAIT2();
        } else if (ch + 1 < NCH) {
            CP_WAIT1();
        } else {
            CP_WAIT0();
        }
        __syncthreads();   // single barrier per chunk

        const uint32_t bstg = sbase + (ch & 3) * BCHUNK + eh * 2048 + lane * 16;
        const uint32_t xstg = xfrag0 + (ch & 3) * XCHUNK;

        // preload x for step 0
        float x0, x1, x2, x3;
        LDSF(x0, xstg);
        LDSF(x1, xstg + 16);
        LDSF(x2, xstg + 8 * XSTRIDE);
        LDSF(x3, xstg + 8 * XSTRIDE + 16);

        #pragma unroll
        for (int s4 = 0; s4 < 4; ++s4) {
            // prefetch next step's x before the MMA burst
            float nx0, nx1, nx2, nx3;
            if (s4 < 3) {
                const uint32_t xp = xstg + (s4 + 1) * 32;
                LDSF(nx0, xp);
                LDSF(nx1, xp + 16);
                LDSF(nx2, xp + 8 * XSTRIDE);
                LDSF(nx3, xp + 8 * XSTRIDE + 16);
            }

            uint32_t Ah[4], Am[4];
            split2(x0, Ah[0], Am[0]);
            split2(x2, Ah[1], Am[1]);
            split2(x1, Ah[2], Am[2]);
            split2(x3, Ah[3], Am[3]);

            const uint32_t bb = bstg + s4 * BSTEP;
            uint4 b0, b1, b2, b3;
            LDS128(b0, bb);
            LDS128(b1, bb + 512);
            LDS128(b2, bb + 1024);
            LDS128(b3, bb + 1536);

            // corrections (Am x wh) first -- independent of chx
            MMA(cc[0], Am, b0.x, b0.y);
            MMA(cc[1], Am, b1.x, b1.y);
            MMA(cc[2], Am, b2.x, b2.y);
            MMA(cc[3], Am, b3.x, b3.y);
            // hh chunk terms (restart onto zero C at chunk head)
            if (s4 == 0) {
                MMA_ZC(chx[0], Ah, b0.x, b0.y);
                MMA_ZC(chx[1], Ah, b1.x, b1.y);
                MMA_ZC(chx[2], Ah, b2.x, b2.y);
                MMA_ZC(chx[3], Ah, b3.x, b3.y);
            } else {
                MMA(chx[0], Ah, b0.x, b0.y);
                MMA(chx[1], Ah, b1.x, b1.y);
                MMA(chx[2], Ah, b2.x, b2.y);
                MMA(chx[3], Ah, b3.x, b3.y);
            }
            // corrections (Ah x wm) -- dependent pairs 8 MMAs apart
            MMA(cc[0], Ah, b0.z, b0.w);
            MMA(cc[1], Ah, b1.z, b1.w);
            MMA(cc[2], Ah, b2.z, b2.w);
            MMA(cc[3], Ah, b3.z, b3.w);

            x0 = nx0; x1 = nx1; x2 = nx2; x3 = nx3;
        }
        // rebase: master += chunk (RN fp32, unbiased)
        #pragma unroll
        for (int i = 0; i < 4; ++i)
            #pragma unroll
            for (int j = 0; j < 4; ++j) ms[i][j] += chx[i][j];
        // no trailing barrier: 4-stage ring keeps writers >= 2 stages away
    }
    __syncthreads();   // all compute done before epilogue smem reuse

    // -------- epilogue: logits -> smem, thread-per-token softmax + top-8 ----
    float* L = smemf;   // [128][EPI_STRIDE]
    {
        int r0 = tg * 16 + g;
        #pragma unroll
        for (int j = 0; j < 4; ++j) {
            int n0 = eh * 32 + j * 8 + 2 * t4;
            *reinterpret_cast<float2*>(L + r0 * EPI_STRIDE + n0) =
                make_float2(ms[j][0] + cc[j][0], ms[j][1] + cc[j][1]);
            *reinterpret_cast<float2*>(L + (r0 + 8) * EPI_STRIDE + n0) =
                make_float2(ms[j][2] + cc[j][2], ms[j][3] + cc[j][3]);
        }
    }
    __syncthreads();

    if (tid < TB) {
        float pv[64];
        const float* Lr = L + tid * EPI_STRIDE;
        #pragma unroll
        for (int c = 0; c < 16; ++c) {
            float4 v = *reinterpret_cast<const float4*>(Lr + 4 * c);
            pv[4 * c] = v.x; pv[4 * c + 1] = v.y;
            pv[4 * c + 2] = v.z; pv[4 * c + 3] = v.w;
        }
        float mx = pv[0];
        #pragma unroll
        for (int c = 1; c < 64; ++c) mx = fmaxf(mx, pv[c]);
        float s = 0.0f;
        #pragma unroll
        for (int c = 0; c < 64; ++c) { pv[c] = __expf(pv[c] - mx); s += pv[c]; }
        float inv = 1.0f / s;
        #pragma unroll
        for (int c = 0; c < 64; ++c) pv[c] *= inv;

        const size_t gt = t0 + tid;
        float* pr = out + gt * 64;
        #pragma unroll
        for (int c = 0; c < 16; ++c)
            *reinterpret_cast<float4*>(pr + 4 * c) =
                make_float4(pv[4 * c], pv[4 * c + 1], pv[4 * c + 2], pv[4 * c + 3]);

        // top-8 insertion; strict '>' keeps smaller index on ties (lax.top_k)
        float tv[8]; int ti[8];
        #pragma unroll
        for (int r = 0; r < 8; ++r) { tv[r] = -1.0f; ti[r] = 0; }
        #pragma unroll
        for (int j = 0; j < 64; ++j) {
            float v = pv[j];
            if (v > tv[7]) {
                tv[7] = v; ti[7] = j;
                #pragma unroll
                for (int q = 7; q > 0; --q) {
                    bool sw = tv[q] > tv[q - 1];
                    float fv = sw ? tv[q - 1] : tv[q];
                    int   fi = sw ? ti[q - 1] : ti[q];
                    tv[q - 1] = sw ? tv[q] : tv[q - 1];
                    ti[q - 1] = sw ? ti[q] : ti[q - 1];
                    tv[q] = fv; ti[q] = fi;
                }
            }
        }
        const size_t tvo = (size_t)Ntok * 64;
        const size_t ixo = tvo + (size_t)Ntok * 8;
        *reinterpret_cast<float4*>(out + tvo + gt * 8)     =
            make_float4(tv[0], tv[1], tv[2], tv[3]);
        *reinterpret_cast<float4*>(out + tvo + gt * 8 + 4) =
            make_float4(tv[4], tv[5], tv[6], tv[7]);
        *reinterpret_cast<float4*>(out + ixo + gt * 8)     =
            make_float4((float)ti[0], (float)ti[1], (float)ti[2], (float)ti[3]);
        *reinterpret_cast<float4*>(out + ixo + gt * 8 + 4) =
            make_float4((float)ti[4], (float)ti[5], (float)ti[6], (float)ti[7]);
    }
}

extern "C" void kernel_launch(void* const* d_in, const int* in_sizes, int n_in,
                              void* d_out, int out_size) {
    const float* x = (const float*)d_in[0];
    const float* w = (const float*)d_in[1];
    float* out = (float*)d_out;
    int Ntok = in_sizes[0] / D;     // 32768

    cudaFuncSetAttribute(moe_gate, cudaFuncAttributeMaxDynamicSharedMemorySize, SMEM_SZ);
    prep_bfrag<<<(256 * 8 * 32 + 255) / 256, 256>>>(w);
    moe_gate<<<Ntok / TB, 512, SMEM_SZ>>>(x, out, Ntok);
}

// round 13
// speedup vs baseline: 1.0831x; 1.0831x over previous
#include <cuda_runtime.h>
#include <cstdint>

// ============================================================================
// Router gate: x [32768, 2048] f32, w [64, 2048] f32.
// logits = x @ w^T ; probs = softmax ; top-8 vals + indices.
// Out: [probs N*64 | top_vals N*8 | indices(float) N*8]
//
// mma m16n8k8 TF32, 2-way split (x=xh+xm, w=wh+wm):
//   xh*wh -> chunk accumulator, rebased every k32 into master via RN FADD
//   xh*wm + xm*wh -> separate small-magnitude accumulator
// R13: R12 with the staging bug fixed (B copy loop: 4 passes x 256 thr x 16B
//      = exactly 16KB; R12 wrote 32KB and clobbered the ring).
//      TB=64, 256 threads, 2 CTAs/SM -> two independent barrier domains.
// ============================================================================

#define D 2048
#define TB 64             // tokens per CTA
#define NCH 64            // k32 chunks
#define BSTEP 4096        // B frag bytes per step
#define BCHUNK 16384      // 4 steps
#define XSTRIDE 144       // bytes per x row: 36 floats (CF swizzle)
#define XCHUNK 9216       // 64 rows * 144
#define XB 65536          // x region base (after 4 B stages)
#define EPI_STRIDE 68
#define SMEM_SZ (XB + 4 * XCHUNK)   // 102400 per CTA -> 2 CTAs/SM

// weights split into tf32 h/m, HMMA B-fragment order:
// [step(256)][tile(8)][lane(32)] x uint4(bh0, bh1, bm0, bm1)
__device__ __align__(16) unsigned char g_bfrag[256 * BSTEP];

static __device__ __forceinline__ uint32_t smem_u32(const void* p) {
    uint32_t a;
    asm("{ .reg .u64 t; cvta.to.shared.u64 t, %1; cvt.u32.u64 %0, t; }"
        : "=r"(a) : "l"(p));
    return a;
}
static __device__ __forceinline__ void split2(float v, uint32_t& h, uint32_t& m) {
    asm("cvt.rna.tf32.f32 %0, %1;" : "=r"(h) : "f"(v));
    float r = v - __uint_as_float(h);
    asm("cvt.rna.tf32.f32 %0, %1;" : "=r"(m) : "f"(r));
}

#define MMA(d, a, b0_, b1_) \
    asm volatile("mma.sync.aligned.m16n8k8.row.col.f32.tf32.tf32.f32 " \
        "{%0,%1,%2,%3}, {%4,%5,%6,%7}, {%8,%9}, {%0,%1,%2,%3};" \
        : "+f"((d)[0]), "+f"((d)[1]), "+f"((d)[2]), "+f"((d)[3]) \
        : "r"((a)[0]), "r"((a)[1]), "r"((a)[2]), "r"((a)[3]), "r"(b0_), "r"(b1_))
#define MMA_ZC(d, a, b0_, b1_) \
    asm volatile("mma.sync.aligned.m16n8k8.row.col.f32.tf32.tf32.f32 " \
        "{%0,%1,%2,%3}, {%4,%5,%6,%7}, {%8,%9}, {%10,%10,%10,%10};" \
        : "=f"((d)[0]), "=f"((d)[1]), "=f"((d)[2]), "=f"((d)[3]) \
        : "r"((a)[0]), "r"((a)[1]), "r"((a)[2]), "r"((a)[3]), "r"(b0_), "r"(b1_), \
          "f"(0.0f))

#define CP16(s, g) \
    asm volatile("cp.async.cg.shared.global [%0], [%1], 16;" :: "r"(s), "l"(g) : "memory")
#define CP_COMMIT() asm volatile("cp.async.commit_group;" ::: "memory")
#define CP_WAIT2()  asm volatile("cp.async.wait_group 2;" ::: "memory")
#define CP_WAIT1()  asm volatile("cp.async.wait_group 1;" ::: "memory")
#define CP_WAIT0()  asm volatile("cp.async.wait_group 0;" ::: "memory")
#define LDS128(v, a) \
    asm volatile("ld.shared.v4.b32 {%0,%1,%2,%3}, [%4];" \
        : "=r"((v).x), "=r"((v).y), "=r"((v).z), "=r"((v).w) : "r"(a))
#define LDSF(v, a) \
    asm volatile("ld.shared.f32 %0, [%1];" : "=f"(v) : "r"(a))

// ---------------- weight prep ----------------
__global__ void prep_bfrag(const float* __restrict__ w) {
    int i = blockIdx.x * blockDim.x + threadIdx.x;   // (step*8 + tile)*32 + lane
    if (i >= 256 * 8 * 32) return;
    int lane = i & 31;
    int tile = (i >> 5) & 7;
    int step = i >> 8;
    int e = tile * 8 + (lane >> 2);
    int tq = lane & 3;
    int k0 = step * 8;
    const float* wr = w + (size_t)e * D;
    uint32_t h0, m0, h1, m1;
    split2(wr[k0 + tq],     h0, m0);
    split2(wr[k0 + tq + 4], h1, m1);
    *reinterpret_cast<uint4*>(g_bfrag + step * BSTEP + tile * 512 + lane * 16) =
        make_uint4(h0, h1, m0, m1);
}

// stage chunk c into ring stage s (B 16KB + X 9KB), one commit group
static __device__ __forceinline__ void stage_chunk(uint32_t sbase,
                                                   const unsigned char* xg,
                                                   int c, int s, int tid) {
    const unsigned char* bsrc = g_bfrag + (size_t)c * BCHUNK;
    uint32_t bd = sbase + s * BCHUNK;
    uint32_t xd = sbase + XB + s * XCHUNK;
    size_t kb = (size_t)c * 128;   // 32 floats
    #pragma unroll
    for (int p = 0; p < 4; ++p) {              // 4 x 256 x 16B = 16KB exactly
        int u = tid + p * 256;
        CP16(bd + u * 16, bsrc + u * 16);
    }
    #pragma unroll
    for (int p = 0; p < 2; ++p) {              // 512 x 16B: 64 rows x 8 segs
        int u = tid + p * 256;
        int row = u >> 3, seg = u & 7;
        CP16(xd + row * XSTRIDE + seg * 16,
             xg + (size_t)row * (D * 4) + kb + seg * 16);
    }
    CP_COMMIT();
}

// ---------------- main fused kernel ----------------
__global__ void __launch_bounds__(256, 2)
moe_gate(const float* __restrict__ x, float* __restrict__ out, int Ntok) {
    extern __shared__ __align__(16) float smemf[];
    const uint32_t sbase = smem_u32(smemf);
    const int tid = threadIdx.x;
    const int wid = tid >> 5;
    const int lane = tid & 31;
    const int g = lane >> 2;
    const int t4 = lane & 3;
    const int tg = wid >> 1;          // token group 0..3 (16 tokens, m16)
    const int eh = wid & 1;           // expert half 0..1 (32 experts, n32)
    const size_t t0 = (size_t)blockIdx.x * TB;
    const unsigned char* xg = reinterpret_cast<const unsigned char*>(x + t0 * D);

    float chx[4][4], ms[4][4], cc[4][4];
    #pragma unroll
    for (int i = 0; i < 4; ++i)
        #pragma unroll
        for (int j = 0; j < 4; ++j) { ms[i][j] = 0.0f; cc[i][j] = 0.0f; }

    // prologue: stage chunks 0 and 1
    stage_chunk(sbase, xg, 0, 0, tid);
    stage_chunk(sbase, xg, 1, 1, tid);

    // x fragment gather base: rows tg*16 + {g, g+8}
    const uint32_t xfrag0 = sbase + XB + (tg * 16 + g) * XSTRIDE + t4 * 4;

    for (int ch = 0; ch < NCH; ++ch) {
        // deep prefetch: issue chunk ch+2 into stage (ch+2)&3, then wait for ch
        if (ch + 2 < NCH) {
            stage_chunk(sbase, xg, ch + 2, (ch + 2) & 3, tid);
            CP_WAIT2();
        } else if (ch + 1 < NCH) {
            CP_WAIT1();
        } else {
            CP_WAIT0();
        }
        __syncthreads();   // single barrier per chunk (per-CTA domain)

        const uint32_t bstg = sbase + (ch & 3) * BCHUNK + eh * 2048 + lane * 16;
        const uint32_t xstg = xfrag0 + (ch & 3) * XCHUNK;

        // preload x for step 0
        float x0, x1, x2, x3;
        LDSF(x0, xstg);
        LDSF(x1, xstg + 16);
        LDSF(x2, xstg + 8 * XSTRIDE);
        LDSF(x3, xstg + 8 * XSTRIDE + 16);

        #pragma unroll
        for (int s4 = 0; s4 < 4; ++s4) {
            // prefetch next step's x before the MMA burst
            float nx0, nx1, nx2, nx3;
            if (s4 < 3) {
                const uint32_t xp = xstg + (s4 + 1) * 32;
                LDSF(nx0, xp);
                LDSF(nx1, xp + 16);
                LDSF(nx2, xp + 8 * XSTRIDE);
                LDSF(nx3, xp + 8 * XSTRIDE + 16);
            }

            uint32_t Ah[4], Am[4];
            split2(x0, Ah[0], Am[0]);
            split2(x2, Ah[1], Am[1]);
            split2(x1, Ah[2], Am[2]);
            split2(x3, Ah[3], Am[3]);

            const uint32_t bb = bstg + s4 * BSTEP;
            uint4 b0, b1, b2, b3;
            LDS128(b0, bb);
            LDS128(b1, bb + 512);
            LDS128(b2, bb + 1024);
            LDS128(b3, bb + 1536);

            // corrections (Am x wh) first -- independent of chx
            MMA(cc[0], Am, b0.x, b0.y);
            MMA(cc[1], Am, b1.x, b1.y);
            MMA(cc[2], Am, b2.x, b2.y);
            MMA(cc[3], Am, b3.x, b3.y);
            // hh chunk terms (restart onto zero C at chunk head)
            if (s4 == 0) {
                MMA_ZC(chx[0], Ah, b0.x, b0.y);
                MMA_ZC(chx[1], Ah, b1.x, b1.y);
                MMA_ZC(chx[2], Ah, b2.x, b2.y);
                MMA_ZC(chx[3], Ah, b3.x, b3.y);
            } else {
                MMA(chx[0], Ah, b0.x, b0.y);
                MMA(chx[1], Ah, b1.x, b1.y);
                MMA(chx[2], Ah, b2.x, b2.y);
                MMA(chx[3], Ah, b3.x, b3.y);
            }
            // corrections (Ah x wm) -- dependent pairs 8 MMAs apart
            MMA(cc[0], Ah, b0.z, b0.w);
            MMA(cc[1], Ah, b1.z, b1.w);
            MMA(cc[2], Ah, b2.z, b2.w);
            MMA(cc[3], Ah, b3.z, b3.w);

            x0 = nx0; x1 = nx1; x2 = nx2; x3 = nx3;
        }
        // rebase: master += chunk (RN fp32, unbiased)
        #pragma unroll
        for (int i = 0; i < 4; ++i)
            #pragma unroll
            for (int j = 0; j < 4; ++j) ms[i][j] += chx[i][j];
        // no trailing barrier: 4-stage ring keeps writers >= 2 stages away
    }
    __syncthreads();   // all compute done before epilogue smem reuse

    // -------- epilogue: logits -> smem, thread-per-token softmax + top-8 ----
    float* L = smemf;   // [64][EPI_STRIDE]
    {
        int r0 = tg * 16 + g;
        #pragma unroll
        for (int j = 0; j < 4; ++j) {
            int n0 = eh * 32 + j * 8 + 2 * t4;
            *reinterpret_cast<float2*>(L + r0 * EPI_STRIDE + n0) =
                make_float2(ms[j][0] + cc[j][0], ms[j][1] + cc[j][1]);
            *reinterpret_cast<float2*>(L + (r0 + 8) * EPI_STRIDE + n0) =
                make_float2(ms[j][2] + cc[j][2], ms[j][3] + cc[j][3]);
        }
    }
    __syncthreads();

    if (tid < TB) {
        float pv[64];
        const float* Lr = L + tid * EPI_STRIDE;
        #pragma unroll
        for (int c = 0; c < 16; ++c) {
            float4 v = *reinterpret_cast<const float4*>(Lr + 4 * c);
            pv[4 * c] = v.x; pv[4 * c + 1] = v.y;
            pv[4 * c + 2] = v.z; pv[4 * c + 3] = v.w;
        }
        float mx = pv[0];
        #pragma unroll
        for (int c = 1; c < 64; ++c) mx = fmaxf(mx, pv[c]);
        float s = 0.0f;
        #pragma unroll
        for (int c = 0; c < 64; ++c) { pv[c] = __expf(pv[c] - mx); s += pv[c]; }
        float inv = 1.0f / s;
        #pragma unroll
        for (int c = 0; c < 64; ++c) pv[c] *= inv;

        const size_t gt = t0 + tid;
        float* pr = out + gt * 64;
        #pragma unroll
        for (int c = 0; c < 16; ++c)
            *reinterpret_cast<float4*>(pr + 4 * c) =
                make_float4(pv[4 * c], pv[4 * c + 1], pv[4 * c + 2], pv[4 * c + 3]);

        // top-8 insertion; strict '>' keeps smaller index on ties (lax.top_k)
        float tv[8]; int ti[8];
        #pragma unroll
        for (int r = 0; r < 8; ++r) { tv[r] = -1.0f; ti[r] = 0; }
        #pragma unroll
        for (int j = 0; j < 64; ++j) {
            float v = pv[j];
            if (v > tv[7]) {
                tv[7] = v; ti[7] = j;
                #pragma unroll
                for (int q = 7; q > 0; --q) {
                    bool sw = tv[q] > tv[q - 1];
                    float fv = sw ? tv[q - 1] : tv[q];
                    int   fi = sw ? ti[q - 1] : ti[q];
                    tv[q - 1] = sw ? tv[q] : tv[q - 1];
                    ti[q - 1] = sw ? ti[q] : ti[q - 1];
                    tv[q] = fv; ti[q] = fi;
                }
            }
        }
        const size_t tvo = (size_t)Ntok * 64;
        const size_t ixo = tvo + (size_t)Ntok * 8;
        *reinterpret_cast<float4*>(out + tvo + gt * 8)     =
            make_float4(tv[0], tv[1], tv[2], tv[3]);
        *reinterpret_cast<float4*>(out + tvo + gt * 8 + 4) =
            make_float4(tv[4], tv[5], tv[6], tv[7]);
        *reinterpret_cast<float4*>(out + ixo + gt * 8)     =
            make_float4((float)ti[0], (float)ti[1], (float)ti[2], (float)ti[3]);
        *reinterpret_cast<float4*>(out + ixo + gt * 8 + 4) =
            make_float4((float)ti[4], (float)ti[5], (float)ti[6], (float)ti[7]);
    }
}

extern "C" void kernel_launch(void* const* d_in, const int* in_sizes, int n_in,
                              void* d_out, int out_size) {
    const float* x = (const float*)d_in[0];
    const float* w = (const float*)d_in[1];
    float* out = (float*)d_out;
    int Ntok = in_sizes[0] / D;     // 32768

    cudaFuncSetAttribute(moe_gate, cudaFuncAttributeMaxDynamicSharedMemorySize, SMEM_SZ);
    prep_bfrag<<<(256 * 8 * 32 + 255) / 256, 256>>>(w);
    moe_gate<<<Ntok / TB, 256, SMEM_SZ>>>(x, out, Ntok);
}